// round 13
// baseline (speedup 1.0000x reference)
#include <cuda_runtime.h>
#include <cuda_fp16.h>
#include <cstdint>

// Problem constants
#define B_  16
#define I_  2048
#define K_  16      // A_IN
#define O_  64
#define A_  32
#define N_  2048    // O_*A_

// votes kernel tiling
#define NI  16              // input capsules per CTA
#define TN  512             // n-tile
#define NT  (N_/TN)         // 4
#define IC  (I_/NI)         // 128
#define STG 3               // cp.async pipeline stages

// route kernel tiling
#define TI3 32              // i's per CTA
#define IC3 (I_/TI3)        // 64
#define TT  8               // i-tile (phase granularity)

// ---- scratch (device globals: no cudaMalloc allowed) ----
__device__ __half g_votes[(size_t)B_ * I_ * N_];        // 128 MB fp16 votes
__device__ float  g_part1[(size_t)IC * B_ * N_];        // 16 MB
__device__ float  g_part2[(size_t)IC3 * B_ * N_];       // 8 MB
__device__ float  g_part3[(size_t)IC3 * B_ * N_];       // 8 MB
__device__ float  g_cum0[B_ * N_];                      // act0
__device__ float  g_cum1[B_ * N_];                      // act0 + act1

// ---- f32x2 packed-math helpers (proven in R2) ----
using u64 = unsigned long long;
__device__ __forceinline__ void fma2(u64& d, u64 a, u64 b) {
    asm("fma.rn.f32x2 %0, %1, %2, %0;" : "+l"(d) : "l"(a), "l"(b));
}
__device__ __forceinline__ void add2(u64& d, u64 a) {
    asm("add.rn.f32x2 %0, %1, %0;" : "+l"(d) : "l"(a));
}
__device__ __forceinline__ float2 unpack2(u64 v) {
    float2 f;
    asm("mov.b64 {%0, %1}, %2;" : "=f"(f.x), "=f"(f.y) : "l"(v));
    return f;
}
__device__ __forceinline__ void cpasync16(uint32_t s, const void* g) {
    asm volatile("cp.async.cg.shared.global [%0], [%1], 16;" :: "r"(s), "l"(g) : "memory");
}
__device__ __forceinline__ void cpcommit() { asm volatile("cp.async.commit_group;" ::: "memory"); }
template<int N_OUT>
__device__ __forceinline__ void cpwait() { asm volatile("cp.async.wait_group %0;" :: "n"(N_OUT) : "memory"); }

// =====================================================================
// votes[b,i,n] = sum_k x[b,i,k]*W[i,k,n], f32x2 compute, fp16 store.
// 3-stage cp.async pipeline, one barrier per iteration.
// grid (NT, IC), 256 threads. dyn smem = 3*(32KB W + 2KB x) = 104448 B.
// =====================================================================
__global__ __launch_bounds__(256, 2) void votes_kernel(const float* __restrict__ x,
                                                       const float* __restrict__ w) {
    extern __shared__ float smem[];
    float2* Xs = (float2*)(smem + STG * 16 * TN);

    const int tid = threadIdx.x;
    const int nt  = blockIdx.x;
    const int ic  = blockIdx.y;
    const int tn  = tid & 127;
    const int bg  = tid >> 7;
    const int b0  = bg * 8;
    const int i0  = ic * NI;
    const int bb  = tid >> 4, kk = tid & 15;

    const uint32_t wbase = (uint32_t)__cvta_generic_to_shared(smem);

    auto stage = [&](int ii, int s) {
        const float4* wsrc = (const float4*)(w + (size_t)(i0 + ii) * K_ * N_ + nt * TN);
        const uint32_t wdst = wbase + s * (16 * TN * 4);
        #pragma unroll
        for (int p = tid; p < K_ * (TN / 4); p += 256)
            cpasync16(wdst + p * 16, &wsrc[(p >> 7) * (N_ / 4) + (p & 127)]);
        float xv = x[((size_t)bb * I_ + (i0 + ii)) * K_ + kk];
        Xs[s * 256 + kk * 16 + bb] = make_float2(xv, xv);
    };

    stage(0, 0); cpcommit();
    stage(1, 1); cpcommit();

    u64 accsum[8][2];
    #pragma unroll
    for (int j = 0; j < 8; ++j) { accsum[j][0] = 0ull; accsum[j][1] = 0ull; }

    for (int ii = 0; ii < NI; ++ii) {
        cpwait<1>();            // buf[ii%3] data complete
        __syncthreads();        // everyone done with buf[(ii-1)%3]; staged data visible
        if (ii + 2 < NI) stage(ii + 2, (ii + 2) % STG);
        cpcommit();

        const float*  Wc = smem + (ii % STG) * 16 * TN;
        const float2* Xc = Xs + (ii % STG) * 256;

        u64 acc[8][2];
        #pragma unroll
        for (int j = 0; j < 8; ++j) { acc[j][0] = 0ull; acc[j][1] = 0ull; }

        #pragma unroll 4
        for (int k = 0; k < K_; ++k) {
            ulonglong2 wv = *(const ulonglong2*)&Wc[k * TN + tn * 4];
            #pragma unroll
            for (int j = 0; j < 8; ++j) {
                u64 xb = *(const u64*)&Xc[k * 16 + b0 + j];   // broadcast LDS.64
                fma2(acc[j][0], xb, wv.x);
                fma2(acc[j][1], xb, wv.y);
            }
        }

        const int i = i0 + ii;
        #pragma unroll
        for (int j = 0; j < 8; ++j) {
            float2 f01 = unpack2(acc[j][0]);
            float2 f23 = unpack2(acc[j][1]);
            __half2 h0 = __floats2half2_rn(f01.x, f01.y);
            __half2 h1 = __floats2half2_rn(f23.x, f23.y);
            uint2 pk;
            pk.x = *reinterpret_cast<unsigned*>(&h0);
            pk.y = *reinterpret_cast<unsigned*>(&h1);
            size_t voff = ((size_t)(b0 + j) * I_ + i) * N_ + nt * TN + tn * 4;
            *reinterpret_cast<uint2*>(&g_votes[voff]) = pk;
            add2(accsum[j][0], acc[j][0]);
            add2(accsum[j][1], acc[j][1]);
        }
    }

    // dump register partials (plain 128-bit stores via typed pointer)
    #pragma unroll
    for (int j = 0; j < 8; ++j) {
        float2 s01 = unpack2(accsum[j][0]);
        float2 s23 = unpack2(accsum[j][1]);
        *(float4*)&g_part1[((size_t)ic * B_ + (b0 + j)) * N_ + nt * TN + tn * 4] =
            make_float4(s01.x, s01.y, s23.x, s23.y);
    }
}

// =====================================================================
// route pass. grid (IC3, B_), 256 threads. rev flips chunk+tile order so
// consecutive passes zigzag through g_votes for L2 reuse.
// =====================================================================
__global__ __launch_bounds__(256) void route_kernel(const float* __restrict__ cum,
                                                    float* __restrict__ part, int rev) {
    const int tid  = threadIdx.x;
    const int b    = blockIdx.y;
    const int ch   = rev ? (IC3 - 1 - (int)blockIdx.x) : (int)blockIdx.x;
    const int n0   = tid * 8;
    const int o    = tid >> 2;
    const int lane = tid & 31;
    const int wrp  = tid >> 5;

    __shared__ float sl[TT][O_];
    __shared__ float sr[TT][O_];

    float av[8];
    {
        const float4* cp4 = (const float4*)(cum + b * N_ + n0);
        float4 a0 = cp4[0], a1 = cp4[1];
        av[0] = a0.x; av[1] = a0.y; av[2] = a0.z; av[3] = a0.w;
        av[4] = a1.x; av[5] = a1.y; av[6] = a1.z; av[7] = a1.w;
    }

    float acc[8] = {0.f, 0.f, 0.f, 0.f, 0.f, 0.f, 0.f, 0.f};
    const __half* vb = g_votes + ((size_t)b * I_ + (size_t)ch * TI3) * N_ + n0;

    for (int tq = 0; tq < TI3 / TT; ++tq) {
        const int t = rev ? (TI3 / TT - 1 - tq) : tq;
        uint4 vr[TT];
        #pragma unroll
        for (int ii = 0; ii < TT; ++ii)
            vr[ii] = *(const uint4*)(vb + ((size_t)(t * TT + ii)) * N_);

        #pragma unroll
        for (int ii = 0; ii < TT; ++ii) {
            float2 f0 = __half22float2(*(__half2*)&vr[ii].x);
            float2 f1 = __half22float2(*(__half2*)&vr[ii].y);
            float2 f2 = __half22float2(*(__half2*)&vr[ii].z);
            float2 f3 = __half22float2(*(__half2*)&vr[ii].w);
            float dp = f0.x * av[0];
            dp = fmaf(f0.y, av[1], dp); dp = fmaf(f1.x, av[2], dp);
            dp = fmaf(f1.y, av[3], dp); dp = fmaf(f2.x, av[4], dp);
            dp = fmaf(f2.y, av[5], dp); dp = fmaf(f3.x, av[6], dp);
            dp = fmaf(f3.y, av[7], dp);
            dp += __shfl_xor_sync(0xffffffffu, dp, 1);
            dp += __shfl_xor_sync(0xffffffffu, dp, 2);
            if ((tid & 3) == 0) sl[ii][o] = dp;
        }
        __syncthreads();

        {   // softmax over 64 o for row `wrp`
            float d0 = sl[wrp][lane], d1 = sl[wrp][lane + 32];
            float mx = fmaxf(d0, d1);
            #pragma unroll
            for (int s = 16; s > 0; s >>= 1) mx = fmaxf(mx, __shfl_xor_sync(0xffffffffu, mx, s));
            float e0 = __expf(d0 - mx), e1 = __expf(d1 - mx);
            float e = e0 + e1;
            #pragma unroll
            for (int s = 16; s > 0; s >>= 1) e += __shfl_xor_sync(0xffffffffu, e, s);
            float inv = 1.f / e;
            sr[wrp][lane]      = e0 * inv;
            sr[wrp][lane + 32] = e1 * inv;
        }
        __syncthreads();

        #pragma unroll
        for (int ii = 0; ii < TT; ++ii) {
            float r = sr[ii][o];
            float2 f0 = __half22float2(*(__half2*)&vr[ii].x);
            float2 f1 = __half22float2(*(__half2*)&vr[ii].y);
            float2 f2 = __half22float2(*(__half2*)&vr[ii].z);
            float2 f3 = __half22float2(*(__half2*)&vr[ii].w);
            acc[0] = fmaf(r, f0.x, acc[0]); acc[1] = fmaf(r, f0.y, acc[1]);
            acc[2] = fmaf(r, f1.x, acc[2]); acc[3] = fmaf(r, f1.y, acc[3]);
            acc[4] = fmaf(r, f2.x, acc[4]); acc[5] = fmaf(r, f2.y, acc[5]);
            acc[6] = fmaf(r, f3.x, acc[6]); acc[7] = fmaf(r, f3.y, acc[7]);
        }
        __syncthreads();
    }

    float4* dst = (float4*)&part[((size_t)ch * B_ + b) * N_ + n0];
    dst[0] = make_float4(acc[0], acc[1], acc[2], acc[3]);
    dst[1] = make_float4(acc[4], acc[5], acc[6], acc[7]);
}

// =====================================================================
// red: reduce 128 chunk-partials -> 4 (grid 128 x 256 = 32768 threads)
// =====================================================================
__global__ __launch_bounds__(256) void red_kernel(const float* __restrict__ src,
                                                  float* __restrict__ dst) {
    const int gid = blockIdx.x * 256 + threadIdx.x;
    const int sl  = gid >> 13;          // 4 slices
    const int f4  = gid & 8191;
    float4 s = make_float4(0.f, 0.f, 0.f, 0.f);
    #pragma unroll 8
    for (int c = sl * 32; c < sl * 32 + 32; ++c) {
        float4 v = ((const float4*)src)[(size_t)c * 8192 + f4];
        s.x += v.x; s.y += v.y; s.z += v.z; s.w += v.w;
    }
    ((float4*)dst)[(size_t)sl * 8192 + f4] = s;
}

// =====================================================================
// squash: grid 512 x 256. CTA covers 16 f4 (= 2 capsules), 16-way chunk
// slicing, smem tree, 8-lane shfl norm.
// =====================================================================
__global__ __launch_bounds__(256) void squash_kernel(const float* __restrict__ part, int nch,
                                                     float scale, const float* __restrict__ bias,
                                                     const float* __restrict__ prev,
                                                     float* __restrict__ out) {
    __shared__ float4 sm[256];
    const int tid = threadIdx.x;
    const int f   = tid & 15;
    const int sl  = tid >> 4;                 // 16 slices
    const int gf4 = blockIdx.x * 16 + f;      // [0, 8192)

    float4 s = make_float4(0.f, 0.f, 0.f, 0.f);
    for (int c = sl; c < nch; c += 16) {
        float4 v = ((const float4*)part)[(size_t)c * 8192 + gf4];
        s.x += v.x; s.y += v.y; s.z += v.z; s.w += v.w;
    }
    sm[tid] = s;
    __syncthreads();

    if (tid < 16) {
        float4 t = sm[tid];
        #pragma unroll
        for (int k = 1; k < 16; ++k) {
            float4 v = sm[tid + 16 * k];
            t.x += v.x; t.y += v.y; t.z += v.z; t.w += v.w;
        }
        const int n4 = gf4 & (N_ / 4 - 1);
        float4 bv = ((const float4*)bias)[n4];
        float4 pre;
        pre.x = t.x * scale + bv.x;
        pre.y = t.y * scale + bv.y;
        pre.z = t.z * scale + bv.z;
        pre.w = t.w * scale + bv.w;
        float ns = pre.x * pre.x + pre.y * pre.y + pre.z * pre.z + pre.w * pre.w;
        ns += __shfl_xor_sync(0xffffu, ns, 1);
        ns += __shfl_xor_sync(0xffffu, ns, 2);
        ns += __shfl_xor_sync(0xffffu, ns, 4);   // 8 lanes = one capsule (32 a)
        const float sc = sqrtf(ns) / (1.f + ns);
        float4 act;
        act.x = pre.x * sc; act.y = pre.y * sc; act.z = pre.z * sc; act.w = pre.w * sc;
        if (prev) {
            float4 pv = ((const float4*)prev)[gf4];
            act.x += pv.x; act.y += pv.y; act.z += pv.z; act.w += pv.w;
        }
        ((float4*)out)[gf4] = act;
    }
}

// =====================================================================
extern "C" void kernel_launch(void* const* d_in, const int* in_sizes, int n_in,
                              void* d_out, int out_size) {
    const float* x    = (const float*)d_in[0];
    const float* w    = (const float*)d_in[1];
    const float* bias = (const float*)d_in[2];
    float* out = (float*)d_out;

    const int smem1 = STG * 16 * TN * (int)sizeof(float) + STG * 256 * (int)sizeof(float2); // 104448
    cudaFuncSetAttribute(votes_kernel, cudaFuncAttributeMaxDynamicSharedMemorySize, smem1);

    void *p1, *p2, *p3, *c0, *c1;
    cudaGetSymbolAddress(&p1, g_part1);
    cudaGetSymbolAddress(&p2, g_part2);
    cudaGetSymbolAddress(&p3, g_part3);
    cudaGetSymbolAddress(&c0, g_cum0);
    cudaGetSymbolAddress(&c1, g_cum1);

    // 0: votes (+ per-chunk sums)
    votes_kernel<<<dim3(NT, IC), 256, smem1>>>(x, w);
    // 1: reduce 128 -> 4 chunks (scratch: p3, overwritten later by route2)
    red_kernel<<<128, 256>>>((const float*)p1, (float*)p3);
    // 2: act0
    squash_kernel<<<512, 256>>>((const float*)p3, 4, 1.f / 64.f, bias, nullptr, (float*)c0);
    // 3: routing iter 1 — descending (votes tail is hot in L2)
    route_kernel<<<dim3(IC3, B_), 256>>>((const float*)c0, (float*)p2, 1);
    // 4: act1 (cumulative)
    squash_kernel<<<512, 256>>>((const float*)p2, IC3, 1.f, bias, (const float*)c0, (float*)c1);
    // 5: routing iter 2 — ascending (route1 tail is hot)   [ncu profiles this one]
    route_kernel<<<dim3(IC3, B_), 256>>>((const float*)c1, (float*)p3, 0);
    // 6: final activation
    squash_kernel<<<512, 256>>>((const float*)p3, IC3, 1.f, bias, nullptr, out);
}